// round 3
// baseline (speedup 1.0000x reference)
#include <cuda_runtime.h>
#include <cstdint>

#define BATCH 256
#define TSTEPS 1024
#define HID 64
#define DIN 3

// Scratch (device globals — no cudaMalloc allowed).
__device__ float g_h2[BATCH * TSTEPS * HID];

typedef unsigned long long u64;

// ---- packed fp32x2 helpers (ptxas never auto-emits FFMA2) ----
__device__ __forceinline__ u64 fma2(u64 a, u64 b, u64 c) {
    u64 d; asm("fma.rn.f32x2 %0, %1, %2, %3;" : "=l"(d) : "l"(a), "l"(b), "l"(c)); return d;
}
__device__ __forceinline__ u64 packf2(float lo, float hi) {
    u64 d; asm("mov.b64 %0, {%1, %2};" : "=l"(d) : "f"(lo), "f"(hi)); return d;
}
__device__ __forceinline__ float2 unpackf2(u64 v) {
    float2 f; asm("mov.b64 {%0, %1}, %2;" : "=f"(f.x), "=f"(f.y) : "l"(v)); return f;
}
// 16B shared load straight into two 64-bit regs
__device__ __forceinline__ void lds2(u64 &a, u64 &b, uint32_t addr) {
    asm volatile("ld.shared.v2.b64 {%0, %1}, [%2];" : "=l"(a), "=l"(b) : "r"(addr));
}

__device__ __forceinline__ float tanh_cell(float x) {
    float ax = fabsf(x);
    float e = __expf(-2.0f * ax);
    float r = __fdividef(1.0f - e, 1.0f + e);
    return copysignf(r, x);
}

// ============================================================================
// Fused 2-layer LSTM. One CTA per 2 sequences, 256 threads, ONE barrier/step.
// Thread layout: g = tid&3 (gate i/f/g/o), m = tid>>2 (cell row 0..63);
// weight row = g*64+m. A cell's 4 gates live in one warp-quad -> SHFL exchange.
// Pipeline: iter t computes layer1 step t and layer2 step t-1.
// h buffers double-buffered: read buf (t+1)&1, write buf t&1.
// Units: 0=l1seq0, 1=l1seq1, 2=l2seq0, 3=l2seq1. Lane updates cell of unit==g.
// ============================================================================
__global__ void __launch_bounds__(256, 1) lstm_fused(
    const float* __restrict__ x,
    const float* __restrict__ Wih0, const float* __restrict__ Whh0,
    const float* __restrict__ bih0, const float* __restrict__ bhh0,
    const float* __restrict__ Wih1, const float* __restrict__ Whh1,
    const float* __restrict__ bih1, const float* __restrict__ bhh1)
{
    __shared__ __align__(16) float sx[2][TSTEPS * DIN];   // 24 KB
    __shared__ __align__(16) float sh1[2][2][HID];        // [buf][seq][k]
    __shared__ __align__(16) float sh2[2][2][HID];
    const int tid = threadIdx.x;
    const int b0 = blockIdx.x * 2;
    const int g = tid & 3;
    const int m = tid >> 2;
    const int row = g * HID + m;

    // stage both sequences' inputs
    {
        const float4* xs0 = (const float4*)(x + (size_t)b0 * TSTEPS * DIN);
        const float4* xs1 = (const float4*)(x + (size_t)(b0 + 1) * TSTEPS * DIN);
        #pragma unroll
        for (int i = 0; i < 3; i++) {
            int idx = tid + i * 256;
            ((float4*)sx[0])[idx] = xs0[idx];
            ((float4*)sx[1])[idx] = xs1[idx];
        }
    }
    // zero both h double-buffers (256 floats each array)
    ((float*)sh1)[tid] = 0.0f;
    ((float*)sh2)[tid] = 0.0f;

    // per-thread weight rows, packed f32x2 along k
    u64 w0[32], wA[32], wB[32];
    {
        const float4* r0 = (const float4*)(Whh0 + row * HID);
        const float4* rA = (const float4*)(Wih1 + row * HID);
        const float4* rB = (const float4*)(Whh1 + row * HID);
        #pragma unroll
        for (int i = 0; i < 16; i++) {
            float4 v = r0[i]; w0[2*i] = packf2(v.x, v.y); w0[2*i+1] = packf2(v.z, v.w);
            float4 a = rA[i]; wA[2*i] = packf2(a.x, a.y); wA[2*i+1] = packf2(a.z, a.w);
            float4 b = rB[i]; wB[2*i] = packf2(b.x, b.y); wB[2*i+1] = packf2(b.z, b.w);
        }
    }
    const float wx0 = Wih0[row * 3 + 0], wx1 = Wih0[row * 3 + 1], wx2 = Wih0[row * 3 + 2];
    const float bias0 = bih0[row] + bhh0[row];
    const float bias1 = bih1[row] + bhh1[row];
    // branchless activation: v = m_out * sigmoid(-a_in * x) + a_out
    //   gate g==2 (tanh): tanh(x) = 2*sig(2x)-1 -> a_in=-2, m_out=2, a_out=-1
    //   else sigmoid:                              a_in=-1, m_out=1, a_out=0
    const bool isT = (g == 2);
    const float a_in  = isT ? -2.0f : -1.0f;
    const float m_out = isT ?  2.0f :  1.0f;
    const float a_out = isT ? -1.0f :  0.0f;

    const uint32_t A_h1 = (uint32_t)__cvta_generic_to_shared(&sh1[0][0][0]);
    const uint32_t A_h2 = (uint32_t)__cvta_generic_to_shared(&sh2[0][0][0]);
    // my h-write address (buf 0); buf stride = 512 B, seq stride = 256 B
    uint32_t a_wr = ((g & 2) ? A_h2 : A_h1) + (uint32_t)(g & 1) * 256u + (uint32_t)m * 4u;
    float* h2p = g_h2 + (size_t)(b0 + (g & 1)) * TSTEPS * HID + m;  // valid for g>=2

    float c = 0.0f;
    const int lane = tid & 31;
    const int qb = lane & ~3;
    __syncthreads();

    uint32_t roff = 512;  // read buf 1 at t=0 (zeroed)
    #pragma unroll 1
    for (int t = 0; t <= TSTEPS; t++) {
        const uint32_t h1s0 = A_h1 + roff, h1s1 = h1s0 + 256;
        const uint32_t h2s0 = A_h2 + roff, h2s1 = h2s0 + 256;
        u64 A0 = 0, A1 = 0, B0 = 0, B1 = 0, C0 = 0, C1 = 0;
        // dot loop — ordered for operand-reuse (a-slot weight / b-slot h sharing)
        #pragma unroll
        for (int kk = 0; kk < 16; kk++) {
            u64 p0, p1, q0, q1, r0, r1, s0, s1;
            lds2(p0, p1, h1s0 + kk * 16);
            lds2(q0, q1, h1s1 + kk * 16);
            lds2(r0, r1, h2s0 + kk * 16);
            lds2(s0, s1, h2s1 + kk * 16);
            A0 = fma2(w0[2*kk],   p0, A0);
            A1 = fma2(w0[2*kk],   q0, A1);   // reuse a: w0
            B1 = fma2(wA[2*kk],   q0, B1);   // reuse b: q0
            B0 = fma2(wA[2*kk],   p0, B0);   // reuse a: wA
            C0 = fma2(wB[2*kk],   r0, C0);
            C1 = fma2(wB[2*kk],   s0, C1);   // reuse a: wB
            A0 = fma2(w0[2*kk+1], p1, A0);
            A1 = fma2(w0[2*kk+1], q1, A1);
            B1 = fma2(wA[2*kk+1], q1, B1);
            B0 = fma2(wA[2*kk+1], p1, B0);
            C0 = fma2(wB[2*kk+1], r1, C0);
            C1 = fma2(wB[2*kk+1], s1, C1);
        }
        const int tx = (t < TSTEPS) ? t : (TSTEPS - 1);
        float2 fA0 = unpackf2(A0), fA1 = unpackf2(A1);
        float2 fB0 = unpackf2(B0), fB1 = unpackf2(B1);
        float2 fC0 = unpackf2(C0), fC1 = unpackf2(C1);
        float xs0v = wx0 * sx[0][tx*3] + wx1 * sx[0][tx*3+1] + wx2 * sx[0][tx*3+2];
        float xs1v = wx0 * sx[1][tx*3] + wx1 * sx[1][tx*3+1] + wx2 * sx[1][tx*3+2];
        float p10 = fA0.x + fA0.y + bias0 + xs0v;
        float p11 = fA1.x + fA1.y + bias0 + xs1v;
        float p20 = (fB0.x + fB0.y) + (fC0.x + fC0.y) + bias1;
        float p21 = (fB1.x + fB1.y) + (fC1.x + fC1.y) + bias1;
        float v10 = fmaf(__fdividef(1.0f, 1.0f + __expf(a_in * p10)), m_out, a_out);
        float v11 = fmaf(__fdividef(1.0f, 1.0f + __expf(a_in * p11)), m_out, a_out);
        float v20 = fmaf(__fdividef(1.0f, 1.0f + __expf(a_in * p20)), m_out, a_out);
        float v21 = fmaf(__fdividef(1.0f, 1.0f + __expf(a_in * p21)), m_out, a_out);

        // gather my unit's (i,f,g,o) from the warp-quad
        float qi, qf, qg, qo;
        {
            float t0 = __shfl_sync(0xffffffffu, v10, qb + 0);
            float t1 = __shfl_sync(0xffffffffu, v10, qb + 1);
            float t2 = __shfl_sync(0xffffffffu, v10, qb + 2);
            float t3 = __shfl_sync(0xffffffffu, v10, qb + 3);
            if (g == 0) { qi = t0; qf = t1; qg = t2; qo = t3; }
            t0 = __shfl_sync(0xffffffffu, v11, qb + 0);
            t1 = __shfl_sync(0xffffffffu, v11, qb + 1);
            t2 = __shfl_sync(0xffffffffu, v11, qb + 2);
            t3 = __shfl_sync(0xffffffffu, v11, qb + 3);
            if (g == 1) { qi = t0; qf = t1; qg = t2; qo = t3; }
            t0 = __shfl_sync(0xffffffffu, v20, qb + 0);
            t1 = __shfl_sync(0xffffffffu, v20, qb + 1);
            t2 = __shfl_sync(0xffffffffu, v20, qb + 2);
            t3 = __shfl_sync(0xffffffffu, v20, qb + 3);
            if (g == 2) { qi = t0; qf = t1; qg = t2; qo = t3; }
            t0 = __shfl_sync(0xffffffffu, v21, qb + 0);
            t1 = __shfl_sync(0xffffffffu, v21, qb + 1);
            t2 = __shfl_sync(0xffffffffu, v21, qb + 2);
            t3 = __shfl_sync(0xffffffffu, v21, qb + 3);
            if (g == 3) { qi = t0; qf = t1; qg = t2; qo = t3; }
        }

        // cell update for my unit: l1 units valid t<T, l2 units valid t>=1
        const bool upd = (g < 2) ? (t < TSTEPS) : (t >= 1);
        if (upd) {
            c = fmaf(qf, c, qi * qg);
            float h = qo * tanh_cell(c);
            asm volatile("st.shared.f32 [%0], %1;"
                         :: "r"(a_wr + (roff ^ 512u)), "f"(h) : "memory");
            if (g >= 2) h2p[(size_t)(t - 1) * HID] = h;
        }
        roff ^= 512u;
        __syncthreads();
    }
}

// ============================================================================
// Output projection: y[r, 0..2] = W_out · h2[r] + b_out.
// ============================================================================
__global__ void __launch_bounds__(256) proj_kernel(
    const float* __restrict__ Wout, const float* __restrict__ bout,
    float* __restrict__ y)
{
    __shared__ float sw[3 * 64];
    __shared__ float sb[3];
    const int tid = threadIdx.x;
    if (tid < 192) sw[tid] = Wout[tid];
    if (tid < 3)   sb[tid] = bout[tid];
    __syncthreads();

    int gg = blockIdx.x * 256 + tid;
    int r = gg >> 4;
    int seg = gg & 15;
    float4 v = *(const float4*)&g_h2[(size_t)r * HID + seg * 4];
    int s4 = seg * 4;
    float a0 = sw[s4] * v.x + sw[s4+1] * v.y + sw[s4+2] * v.z + sw[s4+3] * v.w;
    float a1 = sw[64+s4] * v.x + sw[64+s4+1] * v.y + sw[64+s4+2] * v.z + sw[64+s4+3] * v.w;
    float a2 = sw[128+s4] * v.x + sw[128+s4+1] * v.y + sw[128+s4+2] * v.z + sw[128+s4+3] * v.w;
    #pragma unroll
    for (int o = 8; o > 0; o >>= 1) {
        a0 += __shfl_xor_sync(0xffffffffu, a0, o);
        a1 += __shfl_xor_sync(0xffffffffu, a1, o);
        a2 += __shfl_xor_sync(0xffffffffu, a2, o);
    }
    if (seg == 0) {
        y[(size_t)r * 3 + 0] = a0 + sb[0];
        y[(size_t)r * 3 + 1] = a1 + sb[1];
        y[(size_t)r * 3 + 2] = a2 + sb[2];
    }
}

extern "C" void kernel_launch(void* const* d_in, const int* in_sizes, int n_in,
                              void* d_out, int out_size)
{
    const float* x    = (const float*)d_in[0];
    const float* Wih0 = (const float*)d_in[1];
    const float* Whh0 = (const float*)d_in[2];
    const float* bih0 = (const float*)d_in[3];
    const float* bhh0 = (const float*)d_in[4];
    const float* Wih1 = (const float*)d_in[5];
    const float* Whh1 = (const float*)d_in[6];
    const float* bih1 = (const float*)d_in[7];
    const float* bhh1 = (const float*)d_in[8];
    const float* Wout = (const float*)d_in[9];
    const float* bout = (const float*)d_in[10];
    float* y = (float*)d_out;

    lstm_fused<<<BATCH / 2, 256>>>(x, Wih0, Whh0, bih0, bhh0,
                                   Wih1, Whh1, bih1, bhh1);
    proj_kernel<<<(BATCH * TSTEPS * 16) / 256, 256>>>(Wout, bout, y);
}

// round 5
// speedup vs baseline: 1.0294x; 1.0294x over previous
#include <cuda_runtime.h>
#include <cstdint>

#define BATCH 256
#define TSTEPS 1024
#define HID 64
#define DIN 3

// Scratch (device globals — no cudaMalloc allowed).
__device__ float g_h2[BATCH * TSTEPS * HID];

typedef unsigned long long u64;

// ---- packed fp32x2 helpers (ptxas never auto-emits FFMA2) ----
__device__ __forceinline__ u64 fma2(u64 a, u64 b, u64 c) {
    u64 d; asm("fma.rn.f32x2 %0, %1, %2, %3;" : "=l"(d) : "l"(a), "l"(b), "l"(c)); return d;
}
__device__ __forceinline__ u64 add2(u64 a, u64 b) {
    u64 d; asm("add.rn.f32x2 %0, %1, %2;" : "=l"(d) : "l"(a), "l"(b)); return d;
}
__device__ __forceinline__ u64 packf2(float lo, float hi) {
    u64 d; asm("mov.b64 %0, {%1, %2};" : "=l"(d) : "f"(lo), "f"(hi)); return d;
}
__device__ __forceinline__ float2 unpackf2(u64 v) {
    float2 f; asm("mov.b64 {%0, %1}, %2;" : "=f"(f.x), "=f"(f.y) : "l"(v)); return f;
}
// 16B shared load straight into two 64-bit regs
__device__ __forceinline__ void lds2(u64 &a, u64 &b, uint32_t addr) {
    asm volatile("ld.shared.v2.b64 {%0, %1}, [%2];" : "=l"(a), "=l"(b) : "r"(addr));
}

__device__ __forceinline__ float sigf(float x) {
    float e = __expf(-x);
    return __fdividef(1.0f, 1.0f + e);
}
__device__ __forceinline__ float tanhf_(float x) {
    float ax = fabsf(x);
    float e = __expf(-2.0f * ax);
    float r = __fdividef(1.0f - e, 1.0f + e);
    return copysignf(r, x);
}

// ============================================================================
// Fused 2-layer LSTM (round-2 structure + reuse-ordered FFMA2 stream).
// One CTA per 2 sequences, 256 threads. Thread j owns gate row j of
// Whh0, Wih1, Whh1 (all in registers). Pipeline: iter t = layer1 step t,
// layer2 step t-1. sh1 = h1[t-1] (feeds l1 recurrence AND l2 input GEMV),
// sh2 = h2[t-2]. Cell phase: 256 threads = 256 cells (2 layers x 2 seqs x 64).
// ============================================================================
__global__ void __launch_bounds__(256, 1) lstm_fused(
    const float* __restrict__ x,
    const float* __restrict__ Wih0, const float* __restrict__ Whh0,
    const float* __restrict__ bih0, const float* __restrict__ bhh0,
    const float* __restrict__ Wih1, const float* __restrict__ Whh1,
    const float* __restrict__ bih1, const float* __restrict__ bhh1)
{
    __shared__ __align__(16) float sx[2][TSTEPS * DIN];  // 24 KB
    __shared__ __align__(16) float sh1[2][HID];
    __shared__ __align__(16) float sh2[2][HID];
    __shared__ __align__(16) float sg1[2][256];
    __shared__ __align__(16) float sg2[2][256];
    const int tid = threadIdx.x;
    const int b0 = blockIdx.x * 2;

    // stage both sequences' inputs
    {
        const float4* xs0 = (const float4*)(x + (size_t)b0 * TSTEPS * DIN);
        const float4* xs1 = (const float4*)(x + (size_t)(b0 + 1) * TSTEPS * DIN);
        #pragma unroll
        for (int i = 0; i < 3; i++) {
            int idx = tid + i * 256;
            ((float4*)sx[0])[idx] = xs0[idx];
            ((float4*)sx[1])[idx] = xs1[idx];
        }
    }

    // per-thread weight rows, packed f32x2 along k
    u64 w0[32], wA[32], wB[32];
    {
        const float4* r0 = (const float4*)(Whh0 + tid * HID);
        const float4* rA = (const float4*)(Wih1 + tid * HID);
        const float4* rB = (const float4*)(Whh1 + tid * HID);
        #pragma unroll
        for (int i = 0; i < 16; i++) {
            float4 v = r0[i]; w0[2*i] = packf2(v.x, v.y); w0[2*i+1] = packf2(v.z, v.w);
            float4 a = rA[i]; wA[2*i] = packf2(a.x, a.y); wA[2*i+1] = packf2(a.z, a.w);
            float4 b = rB[i]; wB[2*i] = packf2(b.x, b.y); wB[2*i+1] = packf2(b.z, b.w);
        }
    }
    const float wx0 = Wih0[tid * 3 + 0], wx1 = Wih0[tid * 3 + 1], wx2 = Wih0[tid * 3 + 2];
    const float bias0 = bih0[tid] + bhh0[tid];
    const float bias1 = bih1[tid] + bhh1[tid];
    const int gtype = tid >> 6;

    // cell role: tid -> (layer, seq, m)
    const int cl_layer = tid >> 7;
    const int cl_b = (tid >> 6) & 1;
    const int cl_m = tid & 63;
    float c = 0.0f;

    if (tid < 128) ((float*)sh1)[tid] = 0.0f;
    else           ((float*)sh2)[tid - 128] = 0.0f;

    const uint32_t a_h1s0 = (uint32_t)__cvta_generic_to_shared(&sh1[0][0]);
    const uint32_t a_h1s1 = (uint32_t)__cvta_generic_to_shared(&sh1[1][0]);
    const uint32_t a_h2s0 = (uint32_t)__cvta_generic_to_shared(&sh2[0][0]);
    const uint32_t a_h2s1 = (uint32_t)__cvta_generic_to_shared(&sh2[1][0]);
    float* h2out = &g_h2[(size_t)(b0 + cl_b) * TSTEPS * HID + cl_m];
    __syncthreads();

    #pragma unroll 1
    for (int t = 0; t <= TSTEPS; t++) {
        const int tx = (t < TSTEPS) ? t : (TSTEPS - 1);
        // fold bias + input contribution into accumulator init
        float xs0v = bias0 + wx0*sx[0][tx*3] + wx1*sx[0][tx*3+1] + wx2*sx[0][tx*3+2];
        float xs1v = bias0 + wx0*sx[1][tx*3] + wx1*sx[1][tx*3+1] + wx2*sx[1][tx*3+2];
        u64 A0 = packf2(xs0v, 0.0f);
        u64 A1 = packf2(xs1v, 0.0f);
        u64 B0 = packf2(bias1, 0.0f);
        u64 B1 = 0, C0 = 0, C1 = 0;

        // ---- gate phase: 6 dot products, reuse-slot-ordered ----
        #pragma unroll
        for (int kk = 0; kk < 16; kk++) {
            u64 p0, p1, q0, q1, r0, r1, s0, s1;
            lds2(p0, p1, a_h1s0 + kk * 16);
            lds2(q0, q1, a_h1s1 + kk * 16);
            lds2(r0, r1, a_h2s0 + kk * 16);
            lds2(s0, s1, a_h2s1 + kk * 16);
            // even half: a-slot and b-slot sharing between neighbors
            A0 = fma2(w0[2*kk],   p0, A0);   // a=w0e  b=p0
            B0 = fma2(wA[2*kk],   p0, B0);   // b reuse p0
            B1 = fma2(wA[2*kk],   q0, B1);   // a reuse wAe
            A1 = fma2(w0[2*kk],   q0, A1);   // b reuse q0
            C0 = fma2(wB[2*kk],   r0, C0);   // a=wBe  b=r0
            C1 = fma2(wB[2*kk],   s0, C1);   // a reuse wBe
            // odd half
            A0 = fma2(w0[2*kk+1], p1, A0);
            B0 = fma2(wA[2*kk+1], p1, B0);   // b reuse p1
            B1 = fma2(wA[2*kk+1], q1, B1);   // a reuse wAo
            A1 = fma2(w0[2*kk+1], q1, A1);   // b reuse q1
            C0 = fma2(wB[2*kk+1], r1, C0);
            C1 = fma2(wB[2*kk+1], s1, C1);   // a reuse wBo
        }
        float2 fA0 = unpackf2(A0), fA1 = unpackf2(A1);
        float2 f20 = unpackf2(add2(B0, C0));
        float2 f21 = unpackf2(add2(B1, C1));
        float pre10 = fA0.x + fA0.y;
        float pre11 = fA1.x + fA1.y;
        float pre20 = f20.x + f20.y;
        float pre21 = f21.x + f21.y + bias1;
        float v10, v11, v20, v21;
        if (gtype == 2) {
            v10 = tanhf_(pre10); v11 = tanhf_(pre11);
            v20 = tanhf_(pre20); v21 = tanhf_(pre21);
        } else {
            v10 = sigf(pre10); v11 = sigf(pre11);
            v20 = sigf(pre20); v21 = sigf(pre21);
        }
        sg1[0][tid] = v10; sg1[1][tid] = v11;
        sg2[0][tid] = v20; sg2[1][tid] = v21;
        __syncthreads();

        // ---- cell phase: one cell per thread (warp-uniform roles) ----
        bool active = cl_layer ? (t >= 1) : (t < TSTEPS);
        if (active) {
            const float* Gp = cl_layer ? sg2[cl_b] : sg1[cl_b];
            float iv = Gp[cl_m], fv = Gp[cl_m + 64];
            float gv = Gp[cl_m + 128], ov = Gp[cl_m + 192];
            c = fmaf(fv, c, iv * gv);
            float hn = ov * tanhf_(c);
            if (cl_layer) {
                sh2[cl_b][cl_m] = hn;
                h2out[(size_t)(t - 1) * HID] = hn;
            } else {
                sh1[cl_b][cl_m] = hn;
            }
        }
        __syncthreads();
    }
}

// ============================================================================
// Output projection: y[r, 0..2] = W_out · h2[r] + b_out.
// ============================================================================
__global__ void __launch_bounds__(256) proj_kernel(
    const float* __restrict__ Wout, const float* __restrict__ bout,
    float* __restrict__ y)
{
    __shared__ float sw[3 * 64];
    __shared__ float sb[3];
    const int tid = threadIdx.x;
    if (tid < 192) sw[tid] = Wout[tid];
    if (tid < 3)   sb[tid] = bout[tid];
    __syncthreads();

    int gg = blockIdx.x * 256 + tid;
    int r = gg >> 4;
    int seg = gg & 15;
    float4 v = *(const float4*)&g_h2[(size_t)r * HID + seg * 4];
    int s4 = seg * 4;
    float a0 = sw[s4] * v.x + sw[s4+1] * v.y + sw[s4+2] * v.z + sw[s4+3] * v.w;
    float a1 = sw[64+s4] * v.x + sw[64+s4+1] * v.y + sw[64+s4+2] * v.z + sw[64+s4+3] * v.w;
    float a2 = sw[128+s4] * v.x + sw[128+s4+1] * v.y + sw[128+s4+2] * v.z + sw[128+s4+3] * v.w;
    #pragma unroll
    for (int o = 8; o > 0; o >>= 1) {
        a0 += __shfl_xor_sync(0xffffffffu, a0, o);
        a1 += __shfl_xor_sync(0xffffffffu, a1, o);
        a2 += __shfl_xor_sync(0xffffffffu, a2, o);
    }
    if (seg == 0) {
        y[(size_t)r * 3 + 0] = a0 + sb[0];
        y[(size_t)r * 3 + 1] = a1 + sb[1];
        y[(size_t)r * 3 + 2] = a2 + sb[2];
    }
}

extern "C" void kernel_launch(void* const* d_in, const int* in_sizes, int n_in,
                              void* d_out, int out_size)
{
    const float* x    = (const float*)d_in[0];
    const float* Wih0 = (const float*)d_in[1];
    const float* Whh0 = (const float*)d_in[2];
    const float* bih0 = (const float*)d_in[3];
    const float* bhh0 = (const float*)d_in[4];
    const float* Wih1 = (const float*)d_in[5];
    const float* Whh1 = (const float*)d_in[6];
    const float* bih1 = (const float*)d_in[7];
    const float* bhh1 = (const float*)d_in[8];
    const float* Wout = (const float*)d_in[9];
    const float* bout = (const float*)d_in[10];
    float* y = (float*)d_out;

    lstm_fused<<<BATCH / 2, 256>>>(x, Wih0, Whh0, bih0, bhh0,
                                   Wih1, Whh1, bih1, bhh1);
    proj_kernel<<<(BATCH * TSTEPS * 16) / 256, 256>>>(Wout, bout, y);
}